// round 17
// baseline (speedup 1.0000x reference)
#include <cuda_runtime.h>
#include <math.h>

#define NB     4096
#define ND     4096
#define NCLS   10
#define NSTR   64            // column stripes in K2 (64 cols each)

// Scratch (no allocations -> __device__ globals). Static init covers launch 1;
// K2's last-ticket block re-zeroes the accumulators for every later launch.
__device__ int          g_cnt[NCLS] = {0};        // class counts (K1 atomics)
__device__ double       g_tc[NCLS]  = {0.0};      // sum over class of mn_i*r_i
__device__ double       g_ce        = 0.0;        // CE sum
__device__ unsigned int g_tick      = 0u;         // K2 completion ticket
__device__ int          g_sidx[NCLS][NB];         // class-compacted row indices
__device__ float        g_sr[NCLS][NB];           // class-compacted weights r_i

// ===== K1: per-row min/sum/sumsq ; tid0 classifies + CE + compacted scatter
__global__ void __launch_bounds__(128) k_main(
    const float* __restrict__ grad, const float* __restrict__ outputs,
    const int* __restrict__ y, float* __restrict__ out) {
    int row = blockIdx.x;
    int tid = threadIdx.x;

    // prefetch this row's logits (consumed by tid0 after the reduction sync)
    __shared__ float so[NCLS];
    if (tid < NCLS) so[tid] = outputs[row * NCLS + tid];
    if (row == 0 && tid == 0) { out[0] = 0.0f; g_tick = 0u; }

    const float4* gp = (const float4*)grad + (size_t)row * (ND / 4);
    float mn = 3.0e38f, sum = 0.f, sq = 0.f;
#pragma unroll
    for (int j = 0; j < 8; j++) {
        float4 v = gp[j * 128 + tid];
        mn  = fminf(mn, fminf(fminf(v.x, v.y), fminf(v.z, v.w)));
        sum += (v.x + v.y) + (v.z + v.w);
        sq  += (v.x * v.x + v.y * v.y) + (v.z * v.z + v.w * v.w);
    }
#pragma unroll
    for (int o = 16; o; o >>= 1) {
        mn   = fminf(mn, __shfl_xor_sync(0xffffffffu, mn, o));
        sum += __shfl_xor_sync(0xffffffffu, sum, o);
        sq  += __shfl_xor_sync(0xffffffffu, sq, o);
    }
    __shared__ float smn[4], ssum[4], ssq[4];
    int w = tid >> 5;
    if ((tid & 31) == 0) { smn[w] = mn; ssum[w] = sum; ssq[w] = sq; }
    __syncthreads();
    if (tid == 0) {
        mn = fminf(fminf(smn[0], smn[1]), fminf(smn[2], smn[3]));
        double s = (double)ssum[0] + ssum[1] + ssum[2] + ssum[3];
        double q = (double)ssq[0] + ssq[1] + ssq[2] + ssq[3];
        double mnd = (double)mn;
        // sum of (g-min)^2 ; the (max-min) scale cancels in cosine similarity
        double var = q - 2.0 * mnd * s + (double)ND * mnd * mnd;
        float rinv = (float)(1.0 / sqrt(var));

        // argmax (strict > == first max, matching jnp.argmax) + fp32 CE
        float mx = so[0]; int am = 0;
#pragma unroll
        for (int c = 1; c < NCLS; c++) {
            float v = so[c];
            if (v > mx) { mx = v; am = c; }
        }
        float e = 0.f;
#pragma unroll
        for (int c = 0; c < NCLS; c++) e += __expf(so[c] - mx);
        float lse = mx + logf(e);           // fp32: ~1e-7 rel per term, ample

        // compacted scatter: order within class is irrelevant to S_c / t_c
        int pos = atomicAdd(&g_cnt[am], 1);
        g_sidx[am][pos] = row;
        g_sr[am][pos]   = rinv;
        atomicAdd(&g_tc[am], mnd * (double)rinv);
        atomicAdd(&g_ce, (double)(lse - so[y[row]]));
    }
}

// ===== K2: pure streaming class column sums + squared-norm fold
// grid (64 stripes, NCLS) x 256 = 640 blocks (~4.3/SM, ~54% occ).
// Block covers 64 cols (16 float4-cols) with 16 row-groups over the
// precompacted class list; smem combine yields the COMPLETE S_c[col];
// block folds -sum((S-t_c)^2)/(2B) into out.
// Last-ticket block re-zeroes the K1 accumulators for the next graph replay.
__global__ void __launch_bounds__(256) k_fused(
    const float* __restrict__ grad, float* __restrict__ out) {
    int tid  = threadIdx.x;
    int c    = blockIdx.y;
    int c4   = tid & 15;             // float4-column within the 64-col stripe
    int grp  = tid >> 4;             // 16 row-groups
    int col  = blockIdx.x * 64 + c4 * 4;

    int n = g_cnt[c];                // broadcast load (uniform)
    const int*   idx = g_sidx[c];
    const float* wv  = g_sr[c];

    // weighted column sum over rows p ≡ grp (mod 16) of the class list
    float4 acc = make_float4(0.f, 0.f, 0.f, 0.f);
    int i = grp;
    for (; i + 48 < n; i += 64) {
        int   i0 = __ldg(idx + i),      i1 = __ldg(idx + i + 16);
        int   i2 = __ldg(idx + i + 32), i3 = __ldg(idx + i + 48);
        float r0 = __ldg(wv + i),       r1 = __ldg(wv + i + 16);
        float r2 = __ldg(wv + i + 32),  r3 = __ldg(wv + i + 48);
        const float4 v0 = *(const float4*)(grad + (size_t)i0 * ND + col);
        const float4 v1 = *(const float4*)(grad + (size_t)i1 * ND + col);
        const float4 v2 = *(const float4*)(grad + (size_t)i2 * ND + col);
        const float4 v3 = *(const float4*)(grad + (size_t)i3 * ND + col);
        acc.x = fmaf(r0, v0.x, acc.x); acc.y = fmaf(r0, v0.y, acc.y);
        acc.z = fmaf(r0, v0.z, acc.z); acc.w = fmaf(r0, v0.w, acc.w);
        acc.x = fmaf(r1, v1.x, acc.x); acc.y = fmaf(r1, v1.y, acc.y);
        acc.z = fmaf(r1, v1.z, acc.z); acc.w = fmaf(r1, v1.w, acc.w);
        acc.x = fmaf(r2, v2.x, acc.x); acc.y = fmaf(r2, v2.y, acc.y);
        acc.z = fmaf(r2, v2.z, acc.z); acc.w = fmaf(r2, v2.w, acc.w);
        acc.x = fmaf(r3, v3.x, acc.x); acc.y = fmaf(r3, v3.y, acc.y);
        acc.z = fmaf(r3, v3.z, acc.z); acc.w = fmaf(r3, v3.w, acc.w);
    }
    for (; i < n; i += 16) {
        int   ii = __ldg(idx + i);
        float r  = __ldg(wv + i);
        const float4 v = *(const float4*)(grad + (size_t)ii * ND + col);
        acc.x = fmaf(r, v.x, acc.x); acc.y = fmaf(r, v.y, acc.y);
        acc.z = fmaf(r, v.z, acc.z); acc.w = fmaf(r, v.w, acc.w);
    }

    // combine the 16 row-groups -> complete S_c for these 64 columns
    __shared__ float4 sp[16][16];
    sp[grp][c4] = acc;
    __syncthreads();

    __shared__ double sd;
    if (tid < 32) {
        double local = 0.0;
        if (tid < 16) {
            float4 S = sp[0][tid];
#pragma unroll
            for (int g2 = 1; g2 < 16; g2++) {
                float4 v = sp[g2][tid];
                S.x += v.x; S.y += v.y; S.z += v.z; S.w += v.w;
            }
            double tcv = g_tc[c];
            double x = (double)S.x - tcv, yv = (double)S.y - tcv;
            double z = (double)S.z - tcv, w  = (double)S.w - tcv;
            local = x * x + yv * yv + z * z + w * w;
        }
#pragma unroll
        for (int o = 16; o; o >>= 1)
            local += __shfl_xor_sync(0xffffffffu, local, o);
        if (tid == 0) sd = local;
    }
    __syncthreads();

    if (tid == 0) {
        // loss = ce/B + P/B + 0.5 - s2/(2B); each block folds its s2 share,
        // the designated block also folds the base. out pre-zeroed by K1.
        double contrib = -sd / (2.0 * (double)NB);
        if (blockIdx.x == 0 && c == 0) {
            double ce = g_ce;
            double P  = 0.0;
            for (int k = 0; k < NCLS; k++) {
                double nc = (double)g_cnt[k];
                P += 0.5 * nc * (nc - 1.0);
            }
            contrib += ce / (double)NB + P / (double)NB + 0.5;
        }
        atomicAdd(out, (float)contrib);

        // last block cleans the K1 accumulators for the next replay
        // (every block's reads of g_cnt/g_tc/g_ce precede its ticket add)
        if (atomicAdd(&g_tick, 1u) == NSTR * NCLS - 1) {
            for (int k = 0; k < NCLS; k++) { g_cnt[k] = 0; g_tc[k] = 0.0; }
            g_ce = 0.0;
        }
    }
}

extern "C" void kernel_launch(void* const* d_in, const int* in_sizes, int n_in,
                              void* d_out, int out_size) {
    (void)out_size;
    const float* outputs = nullptr;
    const float* grad    = nullptr;
    const int*   y       = nullptr;
    for (int i = 0; i < n_in; i++) {
        if      (in_sizes[i] == NB * ND)   grad    = (const float*)d_in[i];
        else if (in_sizes[i] == NB * NCLS) outputs = (const float*)d_in[i];
        else if (in_sizes[i] == NB)        y       = (const int*)d_in[i];
    }
    float* out = (float*)d_out;

    k_main<<<NB, 128>>>(grad, outputs, y, out);
    k_fused<<<dim3(NSTR, NCLS), 256>>>(grad, out);
}